// round 1
// baseline (speedup 1.0000x reference)
#include <cuda_runtime.h>
#include <cuda_bf16.h>

// Problem constants (fixed shapes from setup_inputs)
#define BB      4
#define NPTS    8192
#define SS      2048
#define CC      64
#define NSAMPLE 32
#define R2      0.04f     // 0.2^2
#define OUTCH   (3 + CC)  // 67

// One warp per query point. 8 warps / block.
__global__ __launch_bounds__(256) void qg_kernel(
    const float* __restrict__ xyz,      // [B, N, 3]
    const float* __restrict__ new_xyz,  // [B, S, 3]
    const float* __restrict__ feat,     // [B, C, N]
    float* __restrict__ out)            // [B, 67, S, 32]
{
    __shared__ int sidx[8][NSAMPLE];

    const int warp = threadIdx.x >> 5;
    const int lane = threadIdx.x & 31;
    const int w    = blockIdx.x * 8 + warp;   // global query id in [0, B*S)
    const int b    = w / SS;
    const int s    = w % SS;

    // Query point
    const float* qptr = new_xyz + ((size_t)b * SS + s) * 3;
    const float qx = qptr[0], qy = qptr[1], qz = qptr[2];
    // Replicate reference arithmetic EXACTLY: q2 = (qx*qx + qy*qy) + qz*qz,
    // all plain (non-fused) fp32 ops, since index selection is a hard
    // threshold on a catastrophically-cancelling expression.
    const float q2 = __fadd_rn(__fadd_rn(__fmul_rn(qx, qx), __fmul_rn(qy, qy)),
                               __fmul_rn(qz, qz));

    const float* xb = xyz + (size_t)b * NPTS * 3;

    // --- Ball query: sequential ascending scan with early exit -------------
    int cnt = 0;
    for (int base = 0; base < NPTS; base += 32) {
        const int j = base + lane;                 // NPTS % 32 == 0, always valid
        const float px = __ldg(xb + j * 3 + 0);
        const float py = __ldg(xb + j * 3 + 1);
        const float pz = __ldg(xb + j * 3 + 2);

        const float p2  = __fadd_rn(__fadd_rn(__fmul_rn(px, px), __fmul_rn(py, py)),
                                    __fmul_rn(pz, pz));
        const float qpd = __fadd_rn(__fadd_rn(__fmul_rn(qx, px), __fmul_rn(qy, py)),
                                    __fmul_rn(qz, pz));
        // d2 = (q2 + p2) - 2*qp   (left-to-right like the reference)
        const float d2 = __fadd_rn(__fadd_rn(q2, p2), __fmul_rn(-2.0f, qpd));

        const bool in = d2 < R2;
        const unsigned m = __ballot_sync(0xffffffffu, in);
        if (in) {
            const int pos = cnt + __popc(m & ((1u << lane) - 1u));
            if (pos < NSAMPLE) sidx[warp][pos] = j;
        }
        cnt += __popc(m);
        if (cnt >= NSAMPLE) break;                 // warp-uniform
    }
    __syncwarp();

    // Slot -> index (pad with first; all-zero if empty ball)
    int myidx;
    if (cnt == 0) {
        myidx = 0;
    } else {
        const int total = (cnt < NSAMPLE) ? cnt : NSAMPLE;
        const int first = sidx[warp][0];
        myidx = (lane < total) ? sidx[warp][lane] : first;
    }

    // --- Grouping ----------------------------------------------------------
    // out index: ((b*67 + ch)*S + s)*32 + k     k == lane
    const size_t cs    = (size_t)SS * NSAMPLE;                       // channel stride
    const size_t obase = (((size_t)b * OUTCH) * SS + s) * NSAMPLE + lane;

    // grouped_xyz = xyz[idx] - new_xyz   (plain fp32 subtract, same as ref)
    const float px = __ldg(xb + myidx * 3 + 0);
    const float py = __ldg(xb + myidx * 3 + 1);
    const float pz = __ldg(xb + myidx * 3 + 2);
    out[obase + 0 * cs] = px - qx;
    out[obase + 1 * cs] = py - qy;
    out[obase + 2 * cs] = pz - qz;

    // grouped_features: 64 channels, coalesced 128B store per channel
    const float* fb = feat + (size_t)b * CC * NPTS + myidx;
    float*       ob = out + obase + 3 * cs;
#pragma unroll 8
    for (int c = 0; c < CC; c++) {
        ob[(size_t)c * cs] = __ldg(fb + (size_t)c * NPTS);
    }
}

extern "C" void kernel_launch(void* const* d_in, const int* in_sizes, int n_in,
                              void* d_out, int out_size) {
    const float* xyz      = (const float*)d_in[0];   // [4, 8192, 3]
    const float* new_xyz  = (const float*)d_in[1];   // [4, 2048, 3]
    const float* features = (const float*)d_in[2];   // [4, 64, 8192]
    float* out = (float*)d_out;                      // [4, 67, 2048, 32]

    const int total_warps = BB * SS;                 // 8192 queries
    const int blocks = total_warps / 8;              // 1024 blocks, 8 warps each
    qg_kernel<<<blocks, 256>>>(xyz, new_xyz, features, out);
}

// round 2
// speedup vs baseline: 1.7655x; 1.7655x over previous
#include <cuda_runtime.h>
#include <cuda_bf16.h>

// Problem constants (fixed shapes from setup_inputs)
#define BB      4
#define NPTS    8192
#define SS      2048
#define CC      64
#define NSAMPLE 32
#define R2      0.04f     // 0.2^2
#define OUTCH   (3 + CC)  // 67

// Scratch for transposed features: [B, N, C] = 4*8192*64 floats = 8 MB.
__device__ float g_featT[(size_t)BB * NPTS * CC];

// ---------------------------------------------------------------------------
// Kernel 1: transpose features [B, C, N] -> [B, N, C]
// block (32, 8), grid (N/32, C/32, B). Classic smem tile with pad.
// ---------------------------------------------------------------------------
__global__ __launch_bounds__(256) void transpose_kernel(
    const float* __restrict__ feat)
{
    __shared__ float t[32][33];
    const int n0 = blockIdx.x * 32;
    const int c0 = blockIdx.y * 32;
    const int b  = blockIdx.z;
    const int tx = threadIdx.x, ty = threadIdx.y;

    const float* fb = feat + (size_t)b * CC * NPTS;
#pragma unroll
    for (int i = 0; i < 4; i++) {
        // read coalesced along n
        t[ty + 8 * i][tx] = fb[(size_t)(c0 + ty + 8 * i) * NPTS + (n0 + tx)];
    }
    __syncthreads();
    float* fT = g_featT + (size_t)b * NPTS * CC;
#pragma unroll
    for (int i = 0; i < 4; i++) {
        // write coalesced along c (128B per row-write)
        fT[(size_t)(n0 + ty + 8 * i) * CC + (c0 + tx)] = t[tx][ty + 8 * i];
    }
}

// ---------------------------------------------------------------------------
// Kernel 2: ball query + group. One warp per query, 8 warps/block.
// Scan processes 128 points per chunk (4 ballots), loads batched for MLP.
// Feature gather reads 256B contiguous per sample from g_featT.
// ---------------------------------------------------------------------------
__global__ __launch_bounds__(256) void qg_kernel(
    const float* __restrict__ xyz,      // [B, N, 3]
    const float* __restrict__ new_xyz,  // [B, S, 3]
    float* __restrict__ out)            // [B, 67, S, 32]
{
    __shared__ int sidx[8][NSAMPLE];

    const int warp = threadIdx.x >> 5;
    const int lane = threadIdx.x & 31;
    const int w    = blockIdx.x * 8 + warp;   // query id in [0, B*S)
    const int b    = w / SS;
    const int s    = w % SS;

    const float* qptr = new_xyz + ((size_t)b * SS + s) * 3;
    const float qx = qptr[0], qy = qptr[1], qz = qptr[2];
    // Replicate reference arithmetic EXACTLY (plain rn ops, no contraction):
    const float q2 = __fadd_rn(__fadd_rn(__fmul_rn(qx, qx), __fmul_rn(qy, qy)),
                               __fmul_rn(qz, qz));

    const float* xb = xyz + (size_t)b * NPTS * 3;

    // --- Ball query: ascending scan, 128 points per chunk ------------------
    int cnt = 0;
    for (int base = 0; base < NPTS; base += 128) {
        float px[4], py[4], pz[4];
#pragma unroll
        for (int r = 0; r < 4; r++) {
            const int j = base + 32 * r + lane;
            px[r] = __ldg(xb + j * 3 + 0);
            py[r] = __ldg(xb + j * 3 + 1);
            pz[r] = __ldg(xb + j * 3 + 2);
        }
#pragma unroll
        for (int r = 0; r < 4; r++) {
            const float p2  = __fadd_rn(__fadd_rn(__fmul_rn(px[r], px[r]),
                                                  __fmul_rn(py[r], py[r])),
                                        __fmul_rn(pz[r], pz[r]));
            const float qpd = __fadd_rn(__fadd_rn(__fmul_rn(qx, px[r]),
                                                  __fmul_rn(qy, py[r])),
                                        __fmul_rn(qz, pz[r]));
            const float d2  = __fadd_rn(__fadd_rn(q2, p2),
                                        __fmul_rn(-2.0f, qpd));
            const bool in = d2 < R2;
            const unsigned m = __ballot_sync(0xffffffffu, in);
            if (in) {
                const int pos = cnt + __popc(m & ((1u << lane) - 1u));
                if (pos < NSAMPLE) sidx[warp][pos] = base + 32 * r + lane;
            }
            cnt += __popc(m);
        }
        if (cnt >= NSAMPLE) break;             // warp-uniform
    }
    __syncwarp();

    int myidx;
    if (cnt == 0) {
        myidx = 0;
    } else {
        const int total = (cnt < NSAMPLE) ? cnt : NSAMPLE;
        const int first = sidx[warp][0];
        myidx = (lane < total) ? sidx[warp][lane] : first;
    }

    // --- Grouping -----------------------------------------------------------
    const size_t cs    = (size_t)SS * NSAMPLE;                     // channel stride
    const size_t obase = (((size_t)b * OUTCH) * SS + s) * NSAMPLE + lane;

    // grouped_xyz = xyz[idx] - new_xyz
    const float gx = __ldg(xb + myidx * 3 + 0);
    const float gy = __ldg(xb + myidx * 3 + 1);
    const float gz = __ldg(xb + myidx * 3 + 2);
    out[obase + 0 * cs] = gx - qx;
    out[obase + 1 * cs] = gy - qy;
    out[obase + 2 * cs] = gz - qz;

    // grouped_features: lane k reads 256B contiguous for its sample,
    // stores remain 128B-coalesced per channel across the warp.
    const float4* fT = (const float4*)(g_featT + ((size_t)b * NPTS + (size_t)myidx) * CC);
    float* ob = out + obase + 3 * cs;

    float4 v[16];
#pragma unroll
    for (int i = 0; i < 16; i++) v[i] = __ldg(&fT[i]);
#pragma unroll
    for (int i = 0; i < 16; i++) {
        ob[(size_t)(4 * i + 0) * cs] = v[i].x;
        ob[(size_t)(4 * i + 1) * cs] = v[i].y;
        ob[(size_t)(4 * i + 2) * cs] = v[i].z;
        ob[(size_t)(4 * i + 3) * cs] = v[i].w;
    }
}

extern "C" void kernel_launch(void* const* d_in, const int* in_sizes, int n_in,
                              void* d_out, int out_size) {
    const float* xyz      = (const float*)d_in[0];   // [4, 8192, 3]
    const float* new_xyz  = (const float*)d_in[1];   // [4, 2048, 3]
    const float* features = (const float*)d_in[2];   // [4, 64, 8192]
    float* out = (float*)d_out;                      // [4, 67, 2048, 32]

    dim3 tb(32, 8);
    dim3 tg(NPTS / 32, CC / 32, BB);                 // (256, 2, 4)
    transpose_kernel<<<tg, tb>>>(features);

    const int blocks = (BB * SS) / 8;                // 1024 blocks, 8 warps each
    qg_kernel<<<blocks, 256>>>(xyz, new_xyz, out);
}

// round 3
// speedup vs baseline: 2.0372x; 1.1539x over previous
#include <cuda_runtime.h>
#include <cuda_bf16.h>

// Problem constants (fixed shapes from setup_inputs)
#define BB      4
#define NPTS    8192
#define SS      2048
#define CC      64
#define NSAMPLE 32
#define R2      0.04f     // 0.2^2
#define OUTCH   (3 + CC)  // 67

// Scratch: transposed features [B, N, C] (8 MB) and SoA xyz [B, 3, N] (384 KB)
__device__ float g_featT[(size_t)BB * NPTS * CC];
__device__ float g_xyzT[(size_t)BB * 3 * NPTS];

// ---------------------------------------------------------------------------
// Kernel 1: transpose features [B,C,N] -> [B,N,C], and (gridDim.y slice 2)
// repack xyz [B,N,3] -> [B,3,N] (SoA).
// block (32, 8), grid (N/32, C/32 + 1, B).
// ---------------------------------------------------------------------------
__global__ __launch_bounds__(256) void transpose_kernel(
    const float* __restrict__ feat,
    const float* __restrict__ xyz)
{
    const int n0 = blockIdx.x * 32;
    const int b  = blockIdx.z;

    if (blockIdx.y == CC / 32) {
        // xyz repack: 32 points (96 floats) per block, threads 0..95
        const int t = threadIdx.y * 32 + threadIdx.x;
        if (t < 96) {
            const float v = __ldg(xyz + ((size_t)b * NPTS + n0) * 3 + t);
            const int c = t % 3, n = n0 + t / 3;
            g_xyzT[((size_t)b * 3 + c) * NPTS + n] = v;
        }
        return;
    }

    __shared__ float tsm[32][33];
    const int c0 = blockIdx.y * 32;
    const int tx = threadIdx.x, ty = threadIdx.y;

    const float* fb = feat + (size_t)b * CC * NPTS;
#pragma unroll
    for (int i = 0; i < 4; i++)
        tsm[ty + 8 * i][tx] = fb[(size_t)(c0 + ty + 8 * i) * NPTS + (n0 + tx)];
    __syncthreads();
    float* fT = g_featT + (size_t)b * NPTS * CC;
#pragma unroll
    for (int i = 0; i < 4; i++)
        fT[(size_t)(n0 + ty + 8 * i) * CC + (c0 + tx)] = tsm[tx][ty + 8 * i];
}

// ---------------------------------------------------------------------------
// Kernel 2: ball query + group. One warp per query, 8 warps/block.
// Scan: SoA xyz, 128 points/chunk (3 coalesced loads per 32-point round).
// Gather: warp-cooperative coalesced row loads staged through padded smem.
// ---------------------------------------------------------------------------
__global__ __launch_bounds__(256) void qg_kernel(
    const float* __restrict__ new_xyz,  // [B, S, 3]
    float* __restrict__ out)            // [B, 67, S, 32]
{
    __shared__ int   sidx[8][NSAMPLE];
    __shared__ float sxyz[8][NSAMPLE][3];
    __shared__ float tile[8][32 * 33];

    const int warp = threadIdx.x >> 5;
    const int lane = threadIdx.x & 31;
    const int w    = blockIdx.x * 8 + warp;   // query id in [0, B*S)
    const int b    = w / SS;
    const int s    = w % SS;

    const float* qptr = new_xyz + ((size_t)b * SS + s) * 3;
    const float qx = qptr[0], qy = qptr[1], qz = qptr[2];
    // Reference arithmetic EXACTLY (plain rn ops, no contraction):
    const float q2 = __fadd_rn(__fadd_rn(__fmul_rn(qx, qx), __fmul_rn(qy, qy)),
                               __fmul_rn(qz, qz));

    const float* xT0 = g_xyzT + ((size_t)b * 3 + 0) * NPTS;
    const float* xT1 = g_xyzT + ((size_t)b * 3 + 1) * NPTS;
    const float* xT2 = g_xyzT + ((size_t)b * 3 + 2) * NPTS;

    // --- Ball query: ascending scan, 128 points per chunk ------------------
    int cnt = 0;
    for (int base = 0; base < NPTS; base += 128) {
        float px[4], py[4], pz[4];
#pragma unroll
        for (int r = 0; r < 4; r++) {
            const int j = base + 32 * r + lane;
            px[r] = __ldg(xT0 + j);
            py[r] = __ldg(xT1 + j);
            pz[r] = __ldg(xT2 + j);
        }
#pragma unroll
        for (int r = 0; r < 4; r++) {
            const float p2  = __fadd_rn(__fadd_rn(__fmul_rn(px[r], px[r]),
                                                  __fmul_rn(py[r], py[r])),
                                        __fmul_rn(pz[r], pz[r]));
            const float qpd = __fadd_rn(__fadd_rn(__fmul_rn(qx, px[r]),
                                                  __fmul_rn(qy, py[r])),
                                        __fmul_rn(qz, pz[r]));
            const float d2  = __fadd_rn(__fadd_rn(q2, p2),
                                        __fmul_rn(-2.0f, qpd));
            const bool in = d2 < R2;
            const unsigned m = __ballot_sync(0xffffffffu, in);
            if (in) {
                const int pos = cnt + __popc(m & ((1u << lane) - 1u));
                if (pos < NSAMPLE) {
                    sidx[warp][pos]    = base + 32 * r + lane;
                    sxyz[warp][pos][0] = px[r];
                    sxyz[warp][pos][1] = py[r];
                    sxyz[warp][pos][2] = pz[r];
                }
            }
            cnt += __popc(m);
        }
        if (cnt >= NSAMPLE) break;             // warp-uniform
    }

    // Empty-ball fallback: slot 0 = point 0 (matches reference idx=0)
    if (cnt == 0 && lane == 0) {
        sidx[warp][0]    = 0;
        sxyz[warp][0][0] = __ldg(xT0 + 0);
        sxyz[warp][0][1] = __ldg(xT1 + 0);
        sxyz[warp][0][2] = __ldg(xT2 + 0);
    }
    __syncwarp();

    const int total = (cnt == 0) ? 1 : ((cnt < NSAMPLE) ? cnt : NSAMPLE);
    const int slot  = (lane < total) ? lane : 0;     // pad with first
    const int myidx = sidx[warp][slot];

    // --- Output addressing --------------------------------------------------
    const size_t cs    = (size_t)SS * NSAMPLE;
    const size_t obase = (((size_t)b * OUTCH) * SS + s) * NSAMPLE + lane;

    // grouped_xyz = xyz[idx] - new_xyz (coords captured during scan)
    out[obase + 0 * cs] = sxyz[warp][slot][0] - qx;
    out[obase + 1 * cs] = sxyz[warp][slot][1] - qy;
    out[obase + 2 * cs] = sxyz[warp][slot][2] - qz;

    // --- grouped_features: cooperative coalesced gather ---------------------
    // Half-row (32 ch = 128B) per sample loaded coalesced (1 wavefront),
    // staged into padded smem, read back transposed conflict-free.
    const float* fT = g_featT + (size_t)b * NPTS * CC;
    float*       ob = out + obase + 3 * cs;

#pragma unroll
    for (int h = 0; h < 2; h++) {
        // load 32 sample half-rows, 8 at a time (MLP=8/lane, reg-friendly)
#pragma unroll
        for (int m0 = 0; m0 < 32; m0 += 8) {
            float v[8];
#pragma unroll
            for (int m = 0; m < 8; m++) {
                const int im = __shfl_sync(0xffffffffu, myidx, m0 + m);
                v[m] = __ldg(fT + (size_t)im * CC + h * 32 + lane);
            }
#pragma unroll
            for (int m = 0; m < 8; m++)
                tile[warp][(m0 + m) * 33 + lane] = v[m];
        }
        __syncwarp();
        // store: channel c, lane k = sample k -> coalesced 128B per channel
#pragma unroll
        for (int c = 0; c < 32; c++)
            ob[(size_t)(h * 32 + c) * cs] = tile[warp][lane * 33 + c];
        __syncwarp();
    }
}

extern "C" void kernel_launch(void* const* d_in, const int* in_sizes, int n_in,
                              void* d_out, int out_size) {
    const float* xyz      = (const float*)d_in[0];   // [4, 8192, 3]
    const float* new_xyz  = (const float*)d_in[1];   // [4, 2048, 3]
    const float* features = (const float*)d_in[2];   // [4, 64, 8192]
    float* out = (float*)d_out;                      // [4, 67, 2048, 32]

    dim3 tb(32, 8);
    dim3 tg(NPTS / 32, CC / 32 + 1, BB);             // (256, 3, 4)
    transpose_kernel<<<tg, tb>>>(features, xyz);

    const int blocks = (BB * SS) / 8;                // 1024 blocks, 8 warps each
    qg_kernel<<<blocks, 256>>>(new_xyz, out);
}